// round 1
// baseline (speedup 1.0000x reference)
#include <cuda_runtime.h>

// Problem constants
#define T_TOK   8192
#define DMODEL  1024
#define NEXP    8
#define DFF     4096
#define CAP     1280   // int(1.25 * 8192 / 8)

typedef unsigned long long ull;

// ---------------- scratch (device globals; no allocation) ----------------
__device__ float g_disp[(size_t)NEXP * CAP * DMODEL];   // 40 MB
__device__ float g_h   [(size_t)NEXP * CAP * DFF];      // 167 MB
__device__ float g_eo  [(size_t)NEXP * CAP * DMODEL];   // 40 MB
__device__ int   g_idx [T_TOK];
__device__ float g_gate[T_TOK];
__device__ int   g_slot[T_TOK];

// ---------------- packed f32x2 helpers (sm_103a) ----------------
__device__ __forceinline__ ull pk(float x, float y) {
    ull r; asm("mov.b64 %0, {%1, %2};" : "=l"(r) : "f"(x), "f"(y)); return r;
}
__device__ __forceinline__ void upk(ull v, float& x, float& y) {
    asm("mov.b64 {%0, %1}, %2;" : "=f"(x), "=f"(y) : "l"(v));
}
__device__ __forceinline__ ull ffma2(ull a, ull b, ull c) {
    ull d; asm("fma.rn.f32x2 %0, %1, %2, %3;" : "=l"(d) : "l"(a), "l"(b), "l"(c)); return d;
}

// ---------------- 1. gating: logits, softmax, argmax ----------------
// grid 1024 blocks x 256 threads; 1 warp = 1 token
__global__ void gate_kernel(const float* __restrict__ x, const float* __restrict__ wg) {
    __shared__ float wgT[NEXP][DMODEL];   // 32 KB, transposed for conflict-free reads
    int tid = threadIdx.x;
    for (int i = tid; i < DMODEL * NEXP; i += 256)
        wgT[i & 7][i >> 3] = wg[i];
    __syncthreads();

    int warp = tid >> 5, lane = tid & 31;
    int t = blockIdx.x * 8 + warp;
    const float* xr = x + (size_t)t * DMODEL;

    float acc[NEXP];
#pragma unroll
    for (int e = 0; e < NEXP; e++) acc[e] = 0.0f;

    for (int m = lane; m < DMODEL; m += 32) {
        float xv = xr[m];
#pragma unroll
        for (int e = 0; e < NEXP; e++) acc[e] += xv * wgT[e][m];
    }
#pragma unroll
    for (int e = 0; e < NEXP; e++) {
#pragma unroll
        for (int o = 16; o; o >>= 1)
            acc[e] += __shfl_xor_sync(0xffffffffu, acc[e], o);
    }
    if (lane == 0) {
        float mx = acc[0]; int a = 0;
#pragma unroll
        for (int e = 1; e < NEXP; e++)
            if (acc[e] > mx) { mx = acc[e]; a = e; }   // first-max, matches jnp.argmax
        float s = 0.0f;
#pragma unroll
        for (int e = 0; e < NEXP; e++) s += expf(acc[e] - mx);
        g_idx[t]  = a;
        g_gate[t] = 1.0f / s;   // softmax prob of argmax = exp(0)/sum
    }
}

// ---------------- 2. queue positions (per-expert cumsum over token order) ----------------
// single block, 1024 threads, 8 tokens per thread
__global__ void scan_kernel() {
    __shared__ int s[1024];
    int tid = threadIdx.x;
    int loc[8];
    int cnt[NEXP];
#pragma unroll
    for (int e = 0; e < NEXP; e++) cnt[e] = 0;
#pragma unroll
    for (int j = 0; j < 8; j++) {
        loc[j] = g_idx[tid * 8 + j];
        cnt[loc[j]]++;
    }
    int mybase[NEXP];
    for (int e = 0; e < NEXP; e++) {
        s[tid] = cnt[e];
        __syncthreads();
        for (int off = 1; off < 1024; off <<= 1) {
            int v = (tid >= off) ? s[tid - off] : 0;
            __syncthreads();
            s[tid] += v;
            __syncthreads();
        }
        mybase[e] = s[tid] - cnt[e];   // exclusive prefix for this thread's segment
        __syncthreads();
    }
#pragma unroll
    for (int j = 0; j < 8; j++) {
        int e = loc[j];
        int p = mybase[e]++;
        g_slot[tid * 8 + j] = (p < CAP) ? p : -1;   // capacity drop
    }
}

// ---------------- 3. dispatch (gather tokens into [E,C,M]) ----------------
__global__ void gather_kernel(const float* __restrict__ x) {
    int t = blockIdx.x;
    int sl = g_slot[t];
    if (sl < 0) return;
    int e = g_idx[t];
    const float4* src = (const float4*)(x + (size_t)t * DMODEL);
    float4* dst = (float4*)(g_disp + ((size_t)e * CAP + sl) * DMODEL);
    dst[threadIdx.x] = src[threadIdx.x];   // 256 threads x float4 = 1024 floats
}

// ---------------- 4. per-expert SGEMM (fp32, packed f32x2 FMA) ----------------
// 128x128 block tile, BK=8, 256 threads, 8x8 microtile.
// PHASE 1: g_disp[e] (1280xK=1024) @ w1[e] (1024x4096) -> relu+b1 -> g_h
// PHASE 2: g_h[e]    (1280xK=4096) @ w2[e] (4096x1024) -> +b2     -> g_eo
template<int N, int K, bool RELU, int PHASE>
__global__ __launch_bounds__(256, 2)
void sgemm_kernel(const float* __restrict__ Bw, const float* __restrict__ biasb) {
    const int e = blockIdx.z;
    const float* A;
    float* Cc;
    if (PHASE == 1) {
        A  = g_disp + (size_t)e * CAP * DMODEL;
        Cc = g_h    + (size_t)e * CAP * DFF;
    } else {
        A  = g_h    + (size_t)e * CAP * DFF;
        Cc = g_eo   + (size_t)e * CAP * DMODEL;
    }
    const float* B    = Bw    + (size_t)e * K * N;
    const float* bias = biasb + (size_t)e * N;

    const int bm = blockIdx.y * 128;
    const int bn = blockIdx.x * 128;
    const int tid = threadIdx.x;

    __shared__ float As[8][132];   // +4 pad kills store conflicts
    __shared__ float Bs[8][132];

    const int arow = tid >> 1, acol = (tid & 1) * 4;
    const int brow = tid >> 5, bcol = (tid & 31) * 4;
    const float* Aptr = A + (size_t)(bm + arow) * K + acol;
    const float* Bptr = B + (size_t)brow * N + bn + bcol;

    const int ty = tid >> 4, tx = tid & 15;

    ull acc[8][4];
#pragma unroll
    for (int i = 0; i < 8; i++)
#pragma unroll
        for (int j = 0; j < 4; j++) acc[i][j] = 0ull;

    for (int k0 = 0; k0 < K; k0 += 8) {
        float4 av = *(const float4*)Aptr;
        float4 bv = *(const float4*)Bptr;
        Aptr += 8;
        Bptr += (size_t)8 * N;
        __syncthreads();
        As[acol + 0][arow] = av.x;
        As[acol + 1][arow] = av.y;
        As[acol + 2][arow] = av.z;
        As[acol + 3][arow] = av.w;
        *(float4*)&Bs[brow][bcol] = bv;
        __syncthreads();
#pragma unroll
        for (int kk = 0; kk < 8; kk++) {
            float4 a0 = *(const float4*)&As[kk][ty * 8];
            float4 a1 = *(const float4*)&As[kk][ty * 8 + 4];
            float4 b0 = *(const float4*)&Bs[kk][tx * 8];
            float4 b1 = *(const float4*)&Bs[kk][tx * 8 + 4];
            ull bp0 = pk(b0.x, b0.y), bp1 = pk(b0.z, b0.w);
            ull bp2 = pk(b1.x, b1.y), bp3 = pk(b1.z, b1.w);
            float ar[8] = {a0.x, a0.y, a0.z, a0.w, a1.x, a1.y, a1.z, a1.w};
#pragma unroll
            for (int i = 0; i < 8; i++) {
                ull ap = pk(ar[i], ar[i]);
                acc[i][0] = ffma2(ap, bp0, acc[i][0]);
                acc[i][1] = ffma2(ap, bp1, acc[i][1]);
                acc[i][2] = ffma2(ap, bp2, acc[i][2]);
                acc[i][3] = ffma2(ap, bp3, acc[i][3]);
            }
        }
    }

    // epilogue: bias (+relu) + store
    float bvals[8];
#pragma unroll
    for (int j = 0; j < 8; j++) bvals[j] = bias[bn + tx * 8 + j];
#pragma unroll
    for (int i = 0; i < 8; i++) {
        float o[8];
        upk(acc[i][0], o[0], o[1]);
        upk(acc[i][1], o[2], o[3]);
        upk(acc[i][2], o[4], o[5]);
        upk(acc[i][3], o[6], o[7]);
#pragma unroll
        for (int j = 0; j < 8; j++) {
            float v = o[j] + bvals[j];
            if (RELU) v = fmaxf(v, 0.0f);
            o[j] = v;
        }
        float* crow = Cc + (size_t)(bm + ty * 8 + i) * N + bn + tx * 8;
        *(float4*)crow       = make_float4(o[0], o[1], o[2], o[3]);
        *(float4*)(crow + 4) = make_float4(o[4], o[5], o[6], o[7]);
    }
}

// ---------------- 5. combine ----------------
__global__ void combine_kernel(float* __restrict__ out) {
    int t = blockIdx.x;
    int sl = g_slot[t];
    float4* o = (float4*)(out + (size_t)t * DMODEL);
    int i = threadIdx.x;                       // 256 threads x float4
    if (sl < 0) {
        o[i] = make_float4(0.f, 0.f, 0.f, 0.f);   // dropped token -> zeros
        return;
    }
    float g = g_gate[t];
    int e = g_idx[t];
    const float4* src = (const float4*)(g_eo + ((size_t)e * CAP + sl) * DMODEL);
    float4 v = src[i];
    o[i] = make_float4(v.x * g, v.y * g, v.z * g, v.w * g);
}

// ---------------- launch ----------------
extern "C" void kernel_launch(void* const* d_in, const int* in_sizes, int n_in,
                              void* d_out, int out_size) {
    const float* x  = (const float*)d_in[0];   // [4,2048,1024]
    const float* wg = (const float*)d_in[1];   // [1024,8]
    const float* w1 = (const float*)d_in[2];   // [8,1024,4096]
    const float* b1 = (const float*)d_in[3];   // [8,4096]
    const float* w2 = (const float*)d_in[4];   // [8,4096,1024]
    const float* b2 = (const float*)d_in[5];   // [8,1024]
    float* out = (float*)d_out;                // [4,2048,1024]

    gate_kernel<<<T_TOK / 8, 256>>>(x, wg);
    scan_kernel<<<1, 1024>>>();
    gather_kernel<<<T_TOK, 256>>>(x);
    sgemm_kernel<DFF, DMODEL, true, 1><<<dim3(DFF / 128, CAP / 128, NEXP), 256>>>(w1, b1);
    sgemm_kernel<DMODEL, DFF, false, 2><<<dim3(DMODEL / 128, CAP / 128, NEXP), 256>>>(w2, b2);
    combine_kernel<<<T_TOK, 256>>>(out);
}